// round 1
// baseline (speedup 1.0000x reference)
#include <cuda_runtime.h>
#include <cstdint>
#include <cstddef>

// Problem constants
#define NE 8192          // events
#define NP 128           // parents
#define NF 64            // features
#define NH 256           // hidden
#define NN (NP*NE)       // 1,048,576 nodes
#define NO 128           // n_branches * n_features
#define TILE_M 128
#define NTHREADS 512

// Shared-memory layout (floats), all strides padded (+4 mod 32) for conflict-free frag loads
#define A_STRIDE 132
#define H_STRIDE 260
#define SLAB1_STRIDE 260
#define SLAB2_STRIDE 132
#define SLAB1_SIZE (8*SLAB1_STRIDE)
#define SLAB2_SIZE (8*SLAB2_STRIDE)

#define SA_FLOATS (TILE_M*A_STRIDE)          // 16896
#define SH_FLOATS (TILE_M*H_STRIDE)          // 33280
#define SB_FLOATS (2*SLAB1_SIZE)             // 4160 (reused for W2 slabs too)
#define SBIAS_FLOATS (NH+NO)                 // 384
#define SMEM_FLOATS (SA_FLOATS+SH_FLOATS+SB_FLOATS+SBIAS_FLOATS)
#define SMEM_BYTES (SMEM_FLOATS*4)           // 218,880 B < 227 KB

__device__ __forceinline__ float tf32r(float x){
    uint32_t r; asm("cvt.rna.tf32.f32 %0, %1;" : "=r"(r) : "f"(x));
    return __uint_as_float(r);
}

__device__ __forceinline__ void mma8(float c[4], const uint32_t a[4], uint32_t b0, uint32_t b1){
    asm volatile(
        "mma.sync.aligned.m16n8k8.row.col.f32.tf32.tf32.f32 "
        "{%0,%1,%2,%3},{%4,%5,%6,%7},{%8,%9},{%0,%1,%2,%3};\n"
        : "+f"(c[0]), "+f"(c[1]), "+f"(c[2]), "+f"(c[3])
        : "r"(a[0]), "r"(a[1]), "r"(a[2]), "r"(a[3]), "r"(b0), "r"(b1));
}

__global__ void __launch_bounds__(NTHREADS, 1)
fused_branching(const float* __restrict__ x,  const float* __restrict__ gf,
                const float* __restrict__ W1, const float* __restrict__ b1g,
                const float* __restrict__ W2, const float* __restrict__ b2g,
                const int*   __restrict__ pidx, float* __restrict__ out,
                int write_event)
{
    extern __shared__ float sm[];
    float* sA  = sm;
    float* sH  = sA + SA_FLOATS;
    float* sB  = sH + SH_FLOATS;
    float* sb1 = sB + SB_FLOATS;
    float* sb2 = sb1 + NH;

    const int tid  = threadIdx.x;
    const int tile = blockIdx.x;
    const int m0   = tile * TILE_M;

    // ---- identity copy: new_x rows [0, NN) = x (exact fp32, fire-and-forget) ----
    {
        const float4* xs = reinterpret_cast<const float4*>(x)   + (size_t)tile * (TILE_M*NF/4);
        float4*       od = reinterpret_cast<float4*>(out)       + (size_t)tile * (TILE_M*NF/4);
        #pragma unroll
        for (int j = 0; j < 4; j++) od[tid + j*NTHREADS] = xs[tid + j*NTHREADS];
    }
    // ---- event fill: event[i] = i mod NE, written as float32 ----
    if (write_event && tid < 384) {
        int i = tile * 384 + tid;
        out[(size_t)3*NN*NF + i] = (float)(i & (NE-1));
    }
    // ---- biases to smem ----
    if (tid < NH) sb1[tid] = b1g[tid];
    if (tid < NO) sb2[tid] = b2g[tid];

    // ---- gather A tile = [x[pidx] | gf[pidx mod NE]], rounded to tf32 ----
    {
        int r = tid >> 2, q = tid & 3;
        int pi = pidx[m0 + r];
        const float4* src;
        if (q < 2) src = reinterpret_cast<const float4*>(x  + (size_t)pi*NF + q*32);
        else       src = reinterpret_cast<const float4*>(gf + (size_t)(((unsigned)pi) & (NE-1))*NF + (q-2)*32);
        float* dst = sA + r*A_STRIDE + q*32;
        #pragma unroll
        for (int j = 0; j < 8; j++) {
            float4 v = src[j];
            v.x = tf32r(v.x); v.y = tf32r(v.y); v.z = tf32r(v.z); v.w = tf32r(v.w);
            *reinterpret_cast<float4*>(dst + j*4) = v;
        }
    }

    const int warp = tid >> 5, lane = tid & 31;
    const int grp = lane >> 2, tig = lane & 3;
    const int wm = warp >> 2, wn = warp & 3;
    const int mbase = wm * 32;

    // ---- stage W1 slab 0 (8 k-rows x 256) ----
    {
        int kr = tid >> 6, n = (tid & 63) * 4;
        float4 v = *reinterpret_cast<const float4*>(W1 + (size_t)kr*NH + n);
        v.x=tf32r(v.x); v.y=tf32r(v.y); v.z=tf32r(v.z); v.w=tf32r(v.w);
        *reinterpret_cast<float4*>(sB + kr*SLAB1_STRIDE + n) = v;
    }
    __syncthreads();

    // ================= GEMM1: h = relu(A(128x128) @ W1(128x256) + b1) =================
    float acc1[2][8][4];
    #pragma unroll
    for (int mt=0; mt<2; mt++)
        #pragma unroll
        for (int nt=0; nt<8; nt++)
            #pragma unroll
            for (int i=0;i<4;i++) acc1[mt][nt][i]=0.f;

    const int nb1 = wn * 64;
    #pragma unroll 1
    for (int kk = 0; kk < 16; kk++) {
        int buf = (kk & 1) * SLAB1_SIZE;
        float4 pre;
        if (kk < 15) {
            int kr = tid >> 6, n = (tid & 63) * 4;
            pre = *reinterpret_cast<const float4*>(W1 + (size_t)((kk+1)*8 + kr)*NH + n);
        }
        uint32_t A[2][4];
        const uint32_t* sAu = reinterpret_cast<const uint32_t*>(sA);
        #pragma unroll
        for (int mt=0; mt<2; mt++){
            int r0 = mbase + mt*16 + grp;
            int c = kk*8 + tig;
            A[mt][0] = sAu[r0*A_STRIDE + c];
            A[mt][1] = sAu[(r0+8)*A_STRIDE + c];
            A[mt][2] = sAu[r0*A_STRIDE + c + 4];
            A[mt][3] = sAu[(r0+8)*A_STRIDE + c + 4];
        }
        const uint32_t* sBu = reinterpret_cast<const uint32_t*>(sB) + buf;
        #pragma unroll
        for (int nt=0; nt<8; nt++){
            int cn = nb1 + nt*8 + grp;
            uint32_t b0 = sBu[tig*SLAB1_STRIDE + cn];
            uint32_t b1 = sBu[(tig+4)*SLAB1_STRIDE + cn];
            mma8(acc1[0][nt], A[0], b0, b1);
            mma8(acc1[1][nt], A[1], b0, b1);
        }
        if (kk < 15) {
            pre.x=tf32r(pre.x); pre.y=tf32r(pre.y); pre.z=tf32r(pre.z); pre.w=tf32r(pre.w);
            int kr = tid >> 6, n = (tid & 63) * 4;
            *reinterpret_cast<float4*>(sB + (buf ^ SLAB1_SIZE) + kr*SLAB1_STRIDE + n) = pre;
        }
        __syncthreads();
    }

    // ---- epilogue1: bias + relu + tf32-round -> sH ----
    #pragma unroll
    for (int mt=0; mt<2; mt++){
        int r0 = mbase + mt*16 + grp;
        #pragma unroll
        for (int nt=0; nt<8; nt++){
            int c0 = nb1 + nt*8 + 2*tig;
            sH[r0*H_STRIDE + c0]         = tf32r(fmaxf(acc1[mt][nt][0] + sb1[c0],   0.f));
            sH[r0*H_STRIDE + c0 + 1]     = tf32r(fmaxf(acc1[mt][nt][1] + sb1[c0+1], 0.f));
            sH[(r0+8)*H_STRIDE + c0]     = tf32r(fmaxf(acc1[mt][nt][2] + sb1[c0],   0.f));
            sH[(r0+8)*H_STRIDE + c0 + 1] = tf32r(fmaxf(acc1[mt][nt][3] + sb1[c0+1], 0.f));
        }
    }
    // ---- stage W2 slab 0 (sB no longer read by GEMM1) ----
    {
        int kr = tid >> 6, n = (tid & 63) * 2;
        float2 v = *reinterpret_cast<const float2*>(W2 + (size_t)kr*NO + n);
        v.x=tf32r(v.x); v.y=tf32r(v.y);
        *reinterpret_cast<float2*>(sB + kr*SLAB2_STRIDE + n) = v;
    }
    __syncthreads();

    // ================= GEMM2: o = h(128x256) @ W2(256x128) + b2 =================
    float acc2[2][4][4];
    #pragma unroll
    for (int mt=0; mt<2; mt++)
        #pragma unroll
        for (int nt=0; nt<4; nt++)
            #pragma unroll
            for (int i=0;i<4;i++) acc2[mt][nt][i]=0.f;

    const int nb2 = wn * 32;
    #pragma unroll 1
    for (int kk = 0; kk < 32; kk++) {
        int buf = (kk & 1) * SLAB2_SIZE;
        float2 pre;
        if (kk < 31) {
            int kr = tid >> 6, n = (tid & 63) * 2;
            pre = *reinterpret_cast<const float2*>(W2 + (size_t)((kk+1)*8 + kr)*NO + n);
        }
        uint32_t A[2][4];
        const uint32_t* sHu = reinterpret_cast<const uint32_t*>(sH);
        #pragma unroll
        for (int mt=0; mt<2; mt++){
            int r0 = mbase + mt*16 + grp;
            int c = kk*8 + tig;
            A[mt][0] = sHu[r0*H_STRIDE + c];
            A[mt][1] = sHu[(r0+8)*H_STRIDE + c];
            A[mt][2] = sHu[r0*H_STRIDE + c + 4];
            A[mt][3] = sHu[(r0+8)*H_STRIDE + c + 4];
        }
        const uint32_t* sBu = reinterpret_cast<const uint32_t*>(sB) + buf;
        #pragma unroll
        for (int nt=0; nt<4; nt++){
            int cn = nb2 + nt*8 + grp;
            uint32_t b0 = sBu[tig*SLAB2_STRIDE + cn];
            uint32_t b1 = sBu[(tig+4)*SLAB2_STRIDE + cn];
            mma8(acc2[0][nt], A[0], b0, b1);
            mma8(acc2[1][nt], A[1], b0, b1);
        }
        if (kk < 31) {
            pre.x=tf32r(pre.x); pre.y=tf32r(pre.y);
            int kr = tid >> 6, n = (tid & 63) * 2;
            *reinterpret_cast<float2*>(sB + (buf ^ SLAB2_SIZE) + kr*SLAB2_STRIDE + n) = pre;
        }
        __syncthreads();
    }

    // ---- epilogue2: bias + branch-permuted scatter into new_x children region ----
    // node n = m0+row; p = n>>13, e = n&8191; out row = NN + (2p+b)*NE + e, feature f = col&63
    const int p  = m0 >> 13;
    const int e0 = m0 & (NE-1);
    #pragma unroll
    for (int mt=0; mt<2; mt++){
        int r0 = mbase + mt*16 + grp;
        #pragma unroll
        for (int nt=0; nt<4; nt++){
            int c0 = nb2 + nt*8 + 2*tig;
            int br = c0 >> 6;
            int f  = c0 & 63;
            size_t rowbase = (size_t)NN + (size_t)(((p<<1) + br))*NE + e0;
            float2 v;
            v.x = acc2[mt][nt][0] + sb2[c0];
            v.y = acc2[mt][nt][1] + sb2[c0+1];
            *reinterpret_cast<float2*>(out + (rowbase + r0)*NF + f) = v;
            v.x = acc2[mt][nt][2] + sb2[c0];
            v.y = acc2[mt][nt][3] + sb2[c0+1];
            *reinterpret_cast<float2*>(out + (rowbase + r0 + 8)*NF + f) = v;
        }
    }
}

extern "C" void kernel_launch(void* const* d_in, const int* in_sizes, int n_in,
                              void* d_out, int out_size)
{
    const float* x   = (const float*)d_in[0];
    const float* gf  = (const float*)d_in[1];
    const float* W1  = (const float*)d_in[2];
    const float* b1  = (const float*)d_in[3];
    const float* W2  = (const float*)d_in[4];
    const float* b2  = (const float*)d_in[5];
    const int*  pidx = (const int*)d_in[6];
    float* out = (float*)d_out;

    // new_x = 3*NN*NF floats; event (3*NN) appended if out_size includes it
    int write_event = (out_size >= (3*NN*NF + 3*NN)) ? 1 : 0;

    cudaFuncSetAttribute(fused_branching,
                         cudaFuncAttributeMaxDynamicSharedMemorySize, SMEM_BYTES);
    fused_branching<<<NN/TILE_M, NTHREADS, SMEM_BYTES>>>(
        x, gf, W1, b1, W2, b2, pidx, out, write_event);
}

// round 3
// speedup vs baseline: 2.5082x; 2.5082x over previous
#include <cuda_runtime.h>
#include <cuda_fp16.h>
#include <cstdint>
#include <cstddef>

#define NE 8192
#define NF 64
#define NH 256
#define NN (128*8192)
#define NTILES 8192
#define NTHREADS 512

// smem byte offsets (all swizzled f16, no padding)
#define OFF_SA   0u        // A tile   [128 rows][128 k]  f16, row stride 256B
#define OFF_SH   32768u    // h tile   [128 rows][256 k]  f16, row stride 512B
#define OFF_SW1  98304u    // W1^T     [256 n ][128 k]    f16, row stride 256B
#define OFF_SW2  163840u   // W2^T     [128 n ][256 k]    f16, row stride 512B
#define OFF_SB1  229376u
#define OFF_SB2  230400u
#define SMEM_REQ 230912

__device__ __forceinline__ uint32_t smem_u32(const void* p){
    uint32_t a;
    asm("{ .reg .u64 t; cvta.to.shared.u64 t, %1; cvt.u32.u64 %0, t; }" : "=r"(a) : "l"(p));
    return a;
}
__device__ __forceinline__ uint32_t pack_h2(float a, float b){
    __half2 h = __floats2half2_rn(a, b);
    return *reinterpret_cast<uint32_t*>(&h);
}
__device__ __forceinline__ void ldmx4(uint32_t& a0, uint32_t& a1, uint32_t& a2, uint32_t& a3, uint32_t addr){
    asm volatile("ldmatrix.sync.aligned.m8n8.x4.shared.b16 {%0,%1,%2,%3}, [%4];"
                 : "=r"(a0), "=r"(a1), "=r"(a2), "=r"(a3) : "r"(addr));
}
__device__ __forceinline__ uint32_t lds32(uint32_t addr){
    uint32_t v; asm volatile("ld.shared.b32 %0, [%1];" : "=r"(v) : "r"(addr)); return v;
}
__device__ __forceinline__ void sts32(uint32_t addr, uint32_t v){
    asm volatile("st.shared.b32 [%0], %1;" :: "r"(addr), "r"(v) : "memory");
}
__device__ __forceinline__ void sts128(uint32_t addr, uint32_t p0, uint32_t p1, uint32_t p2, uint32_t p3){
    asm volatile("st.shared.v4.b32 [%0], {%1,%2,%3,%4};" :: "r"(addr), "r"(p0), "r"(p1), "r"(p2), "r"(p3) : "memory");
}
__device__ __forceinline__ void mma16(float c[4], uint32_t a0, uint32_t a1, uint32_t a2, uint32_t a3,
                                      uint32_t b0, uint32_t b1){
    asm volatile(
        "mma.sync.aligned.m16n8k16.row.col.f32.f16.f16.f32 "
        "{%0,%1,%2,%3},{%4,%5,%6,%7},{%8,%9},{%0,%1,%2,%3};\n"
        : "+f"(c[0]), "+f"(c[1]), "+f"(c[2]), "+f"(c[3])
        : "r"(a0), "r"(a1), "r"(a2), "r"(a3), "r"(b0), "r"(b1));
}

__global__ void __launch_bounds__(NTHREADS, 1)
fused_h16(const float* __restrict__ x,  const float* __restrict__ gf,
          const float* __restrict__ W1, const float* __restrict__ b1g,
          const float* __restrict__ W2, const float* __restrict__ b2g,
          const int*   __restrict__ pidx, float* __restrict__ out, int write_event)
{
    extern __shared__ char sm[];
    const int tid  = threadIdx.x;
    const int warp = tid >> 5, lane = tid & 31;
    const int grp = lane >> 2, tig = lane & 3;
    const int wm = warp >> 2, wn = warp & 3;
    const int mbase = wm * 32;

    const uint32_t smu  = smem_u32(sm);
    const uint32_t sAu  = smu + OFF_SA;
    const uint32_t sHu  = smu + OFF_SH;
    const uint32_t sW1u = smu + OFF_SW1;
    const uint32_t sW2u = smu + OFF_SW2;
    float* sb1 = (float*)(sm + OFF_SB1);
    float* sb2 = (float*)(sm + OFF_SB2);

    // ================= one-time weight preload (coalesced gmem, swizzled smem) =================
    // W1 global [128 k][256 n] -> sW1 = W1^T [n][k]: byte = n*256 + ((2k &~15)^((n&7)<<4)) + (2k&15)
    for (int i = tid; i < 128 * NH; i += NTHREADS) {
        int k = i >> 8, n = i & 255;
        uint32_t cb = (uint32_t)(2 * k);
        uint32_t off = (uint32_t)n * 256u + ((cb & ~15u) ^ (((uint32_t)n & 7u) << 4)) + (cb & 15u);
        *(half*)(sm + OFF_SW1 + off) = __float2half_rn(W1[i]);
    }
    // W2 global [256 k][128 n] -> sW2 = W2^T [n][k]: byte = n*512 + ((2k&~15)^((n&7)<<4)) + (2k&15)
    for (int i = tid; i < NH * 128; i += NTHREADS) {
        int k = i >> 7, n = i & 127;
        uint32_t cb = (uint32_t)(2 * k);
        uint32_t off = (uint32_t)n * 512u + ((cb & ~15u) ^ (((uint32_t)n & 7u) << 4)) + (cb & 15u);
        *(half*)(sm + OFF_SW2 + off) = __float2half_rn(W2[i]);
    }
    if (tid < NH)  sb1[tid] = b1g[tid];
    if (tid < 128) sb2[tid] = b2g[tid];
    __syncthreads();

    // per-thread constant addresses
    const uint32_t amask = ((uint32_t)(lane & 7)) << 4;       // ldmatrix row swizzle mask
    const uint32_t ahi   = ((uint32_t)(lane >> 4)) << 4;      // k-half select (0 / 16B)
    const uint32_t bmask = ((uint32_t)grp) << 4;               // B row swizzle mask (cn&7 == grp)
    const int lr = lane & 15;

    const uint32_t a1Base0 = sAu + (uint32_t)(mbase + lr) * 256u;
    const uint32_t a1Base1 = a1Base0 + 16u * 256u;
    const uint32_t a2Base0 = sHu + (uint32_t)(mbase + lr) * 512u;
    const uint32_t a2Base1 = a2Base0 + 16u * 512u;

    const int nb1 = wn * 64;
    const int nb2 = wn * 32;
    const uint32_t b1Base = sW1u + (uint32_t)(nb1 + grp) * 256u + (uint32_t)tig * 4u;
    const uint32_t b2Base = sW2u + (uint32_t)(nb2 + grp) * 512u + (uint32_t)tig * 4u;

    // ================= persistent tile loop =================
    for (int t = blockIdx.x; t < NTILES; t += gridDim.x) {
        const int m0 = t << 7;

        // ---- Phase A: warps 0-3 gather A (f16, swizzled); warps 4-15 identity copy + event ----
        if (warp < 4) {
            const int r  = tid;                               // 0..127
            const int pi = pidx[m0 + r];
            const uint32_t rb  = sAu + (uint32_t)r * 256u;
            const uint32_t msk = ((uint32_t)(r & 7)) << 4;
            const float4* xs = (const float4*)(x + (size_t)pi * NF);
            #pragma unroll
            for (int c = 0; c < 8; c++) {
                float4 u = xs[2*c], v = xs[2*c+1];
                sts128(rb + (((uint32_t)(c*16)) ^ msk),
                       pack_h2(u.x,u.y), pack_h2(u.z,u.w), pack_h2(v.x,v.y), pack_h2(v.z,v.w));
            }
            const float4* gs = (const float4*)(gf + (size_t)(((unsigned)pi) & (NE-1)) * NF);
            #pragma unroll
            for (int c = 0; c < 8; c++) {
                float4 u = gs[2*c], v = gs[2*c+1];
                sts128(rb + (((uint32_t)(128 + c*16)) ^ msk),
                       pack_h2(u.x,u.y), pack_h2(u.z,u.w), pack_h2(v.x,v.y), pack_h2(v.z,v.w));
            }
        } else {
            const int tt = tid - 128;                         // 0..383
            const float4* xs = (const float4*)x + (size_t)t * 2048;
            float4*       od = (float4*)out      + (size_t)t * 2048;
            #pragma unroll
            for (int j = 0; j < 6; j++) {
                int idx = tt + j * 384;
                if (idx < 2048) od[idx] = xs[idx];
            }
            if (write_event) {
                int ei = t * 384 + tt;
                out[(size_t)3 * NN * NF + ei] = (float)(ei & (NE - 1));
            }
        }
        __syncthreads();

        // ---- GEMM1: C1(128x256) = A(128x128) @ W1, K=128 in 8 steps ----
        float acc1[2][8][4];
        #pragma unroll
        for (int mt=0; mt<2; mt++)
            #pragma unroll
            for (int nt=0; nt<8; nt++)
                #pragma unroll
                for (int i=0;i<4;i++) acc1[mt][nt][i]=0.f;

        #pragma unroll
        for (int kk = 0; kk < 8; kk++) {
            const uint32_t ksw = (((uint32_t)(kk*32)) + ahi) ^ amask;
            uint32_t A0[4], A1[4];
            ldmx4(A0[0],A0[1],A0[2],A0[3], a1Base0 + ksw);
            ldmx4(A1[0],A1[1],A1[2],A1[3], a1Base1 + ksw);
            const uint32_t k0 = ((uint32_t)(kk*32))      ^ bmask;
            const uint32_t k1 = ((uint32_t)(kk*32 + 16)) ^ bmask;
            #pragma unroll
            for (int nt = 0; nt < 8; nt++) {
                uint32_t b0 = lds32(b1Base + (uint32_t)nt*2048u + k0);
                uint32_t b1 = lds32(b1Base + (uint32_t)nt*2048u + k1);
                mma16(acc1[0][nt], A0[0],A0[1],A0[2],A0[3], b0, b1);
                mma16(acc1[1][nt], A1[0],A1[1],A1[2],A1[3], b0, b1);
            }
        }

        // ---- Epilogue 1: bias + relu + pack f16 -> sH (swizzled) ----
        #pragma unroll
        for (int mt=0; mt<2; mt++){
            const int r0 = mbase + mt*16 + grp;
            const uint32_t rb0 = sHu + (uint32_t)r0 * 512u;
            const uint32_t rb1 = rb0 + 8u * 512u;
            #pragma unroll
            for (int nt=0; nt<8; nt++){
                const int c0 = nb1 + nt*8 + 2*tig;
                const uint32_t csw = (((uint32_t)(nb1*2 + nt*16)) ^ bmask) + (uint32_t)(4*tig);
                float bz0 = sb1[c0], bz1 = sb1[c0+1];
                sts32(rb0 + csw, pack_h2(fmaxf(acc1[mt][nt][0]+bz0,0.f), fmaxf(acc1[mt][nt][1]+bz1,0.f)));
                sts32(rb1 + csw, pack_h2(fmaxf(acc1[mt][nt][2]+bz0,0.f), fmaxf(acc1[mt][nt][3]+bz1,0.f)));
            }
        }
        __syncthreads();

        // ---- GEMM2: C2(128x128) = h(128x256) @ W2, K=256 in 16 steps ----
        float acc2[2][4][4];
        #pragma unroll
        for (int mt=0; mt<2; mt++)
            #pragma unroll
            for (int nt=0; nt<4; nt++)
                #pragma unroll
                for (int i=0;i<4;i++) acc2[mt][nt][i]=0.f;

        #pragma unroll
        for (int kk = 0; kk < 16; kk++) {
            const uint32_t ksw = (((uint32_t)(kk*32)) + ahi) ^ amask;
            uint32_t A0[4], A1[4];
            ldmx4(A0[0],A0[1],A0[2],A0[3], a2Base0 + ksw);
            ldmx4(A1[0],A1[1],A1[2],A1[3], a2Base1 + ksw);
            const uint32_t k0 = ((uint32_t)(kk*32))      ^ bmask;
            const uint32_t k1 = ((uint32_t)(kk*32 + 16)) ^ bmask;
            #pragma unroll
            for (int nt = 0; nt < 4; nt++) {
                uint32_t b0 = lds32(b2Base + (uint32_t)nt*4096u + k0);
                uint32_t b1 = lds32(b2Base + (uint32_t)nt*4096u + k1);
                mma16(acc2[0][nt], A0[0],A0[1],A0[2],A0[3], b0, b1);
                mma16(acc2[1][nt], A1[0],A1[1],A1[2],A1[3], b0, b1);
            }
        }

        // ---- Epilogue 2: bias + branch-permuted scatter ----
        const int p  = m0 >> 13;
        const int e0 = m0 & (NE - 1);
        #pragma unroll
        for (int mt=0; mt<2; mt++){
            const int r0 = mbase + mt*16 + grp;
            #pragma unroll
            for (int nt=0; nt<4; nt++){
                const int c0 = nb2 + nt*8 + 2*tig;
                const int br = c0 >> 6, fc = c0 & 63;
                const size_t rowbase = (size_t)NN + (size_t)(2*p + br) * NE + (size_t)e0;
                float bz0 = sb2[c0], bz1 = sb2[c0+1];
                float2 v0 = { acc2[mt][nt][0] + bz0, acc2[mt][nt][1] + bz1 };
                float2 v1 = { acc2[mt][nt][2] + bz0, acc2[mt][nt][3] + bz1 };
                *(float2*)(out + (rowbase + r0)     * NF + fc) = v0;
                *(float2*)(out + (rowbase + r0 + 8) * NF + fc) = v1;
            }
        }
        __syncthreads();   // protect sA (next gather) and sH (next epilogue-1) reuse
    }
}

extern "C" void kernel_launch(void* const* d_in, const int* in_sizes, int n_in,
                              void* d_out, int out_size)
{
    const float* x   = (const float*)d_in[0];
    const float* gf  = (const float*)d_in[1];
    const float* W1  = (const float*)d_in[2];
    const float* b1  = (const float*)d_in[3];
    const float* W2  = (const float*)d_in[4];
    const float* b2  = (const float*)d_in[5];
    const int*  pidx = (const int*)d_in[6];
    float* out = (float*)d_out;

    int write_event = (out_size >= (3 * NN * NF + 3 * NN)) ? 1 : 0;

    int dev = 0, nsm = 148;
    cudaGetDevice(&dev);
    cudaDeviceGetAttribute(&nsm, cudaDevAttrMultiProcessorCount, dev);
    if (nsm <= 0 || nsm > NTILES) nsm = 148;

    cudaFuncSetAttribute(fused_h16, cudaFuncAttributeMaxDynamicSharedMemorySize, SMEM_REQ);
    fused_h16<<<nsm, NTHREADS, SMEM_REQ>>>(x, gf, W1, b1, W2, b2, pidx, out, write_event);
}

// round 4
// speedup vs baseline: 2.5402x; 1.0128x over previous
#include <cuda_runtime.h>
#include <cuda_fp16.h>
#include <cstdint>
#include <cstddef>

#define NE 8192
#define NF 64
#define NH 256
#define NN (128*8192)
#define NTILES 8192
#define NTHREADS 256

// smem byte offsets (all swizzled f16)
#define OFF_SA   0u        // A tile [128][128k] f16, row stride 256B
#define OFF_SH   32768u    // h tile [128][256k] f16, row stride 512B
#define OFF_SW1  98304u    // W1^T  [256n][128k] f16, row stride 256B
#define OFF_SW2  163840u   // W2^T  [128n][256k] f16, row stride 512B
#define OFF_SB1  229376u
#define OFF_SB2  230400u
#define SMEM_REQ 230912

__device__ __forceinline__ uint32_t smem_u32(const void* p){
    uint32_t a;
    asm("{ .reg .u64 t; cvta.to.shared.u64 t, %1; cvt.u32.u64 %0, t; }" : "=r"(a) : "l"(p));
    return a;
}
__device__ __forceinline__ uint32_t pack_h2(float a, float b){
    __half2 h = __floats2half2_rn(a, b);
    return *reinterpret_cast<uint32_t*>(&h);
}
__device__ __forceinline__ void ldmx4(uint32_t& a0, uint32_t& a1, uint32_t& a2, uint32_t& a3, uint32_t addr){
    asm volatile("ldmatrix.sync.aligned.m8n8.x4.shared.b16 {%0,%1,%2,%3}, [%4];"
                 : "=r"(a0), "=r"(a1), "=r"(a2), "=r"(a3) : "r"(addr));
}
__device__ __forceinline__ uint32_t lds32(uint32_t addr){
    uint32_t v; asm volatile("ld.shared.b32 %0, [%1];" : "=r"(v) : "r"(addr)); return v;
}
__device__ __forceinline__ void sts32(uint32_t addr, uint32_t v){
    asm volatile("st.shared.b32 [%0], %1;" :: "r"(addr), "r"(v) : "memory");
}
__device__ __forceinline__ void sts128(uint32_t addr, uint32_t p0, uint32_t p1, uint32_t p2, uint32_t p3){
    asm volatile("st.shared.v4.b32 [%0], {%1,%2,%3,%4};" :: "r"(addr), "r"(p0), "r"(p1), "r"(p2), "r"(p3) : "memory");
}
__device__ __forceinline__ void mma16(float c[4], uint32_t a0, uint32_t a1, uint32_t a2, uint32_t a3,
                                      uint32_t b0, uint32_t b1){
    asm volatile(
        "mma.sync.aligned.m16n8k16.row.col.f32.f16.f16.f32 "
        "{%0,%1,%2,%3},{%4,%5,%6,%7},{%8,%9},{%0,%1,%2,%3};\n"
        : "+f"(c[0]), "+f"(c[1]), "+f"(c[2]), "+f"(c[3])
        : "r"(a0), "r"(a1), "r"(a2), "r"(a3), "r"(b0), "r"(b1));
}

__global__ void __launch_bounds__(NTHREADS, 1)
fused_h16b(const float* __restrict__ x,  const float* __restrict__ gf,
           const float* __restrict__ W1, const float* __restrict__ b1g,
           const float* __restrict__ W2, const float* __restrict__ b2g,
           const int*   __restrict__ pidx, float* __restrict__ out, int write_event)
{
    extern __shared__ char sm[];
    const int tid  = threadIdx.x;
    const int warp = tid >> 5, lane = tid & 31;
    const int grp = lane >> 2, tig = lane & 3;
    const int wm = warp >> 2, wn = warp & 3;   // 2 x 4 warp grid

    const uint32_t smu  = smem_u32(sm);
    const uint32_t sAu  = smu + OFF_SA;
    const uint32_t sHu  = smu + OFF_SH;
    float* sb1 = (float*)(sm + OFF_SB1);
    float* sb2 = (float*)(sm + OFF_SB2);

    // ---- one-time weight preload (swizzled f16) ----
    for (int i = tid; i < 128 * NH; i += NTHREADS) {
        int k = i >> 8, n = i & 255;
        uint32_t cb = (uint32_t)(2 * k);
        uint32_t off = (uint32_t)n * 256u + ((cb & ~15u) ^ (((uint32_t)n & 7u) << 4)) + (cb & 15u);
        *(half*)(sm + OFF_SW1 + off) = __float2half_rn(W1[i]);
    }
    for (int i = tid; i < NH * 128; i += NTHREADS) {
        int k = i >> 7, n = i & 127;
        uint32_t cb = (uint32_t)(2 * k);
        uint32_t off = (uint32_t)n * 512u + ((cb & ~15u) ^ (((uint32_t)n & 7u) << 4)) + (cb & 15u);
        *(half*)(sm + OFF_SW2 + off) = __float2half_rn(W2[i]);
    }
    sb1[tid] = b1g[tid];
    if (tid < 128) sb2[tid] = b2g[tid];
    __syncthreads();

    // per-thread constants
    const uint32_t amask = ((uint32_t)(lane & 7)) << 4;   // ldmatrix swizzle
    const uint32_t ahi   = ((uint32_t)(lane >> 4)) << 4;  // k-half select
    const uint32_t bmask = ((uint32_t)grp) << 4;          // B / epilogue swizzle
    const int lr = lane & 15;

    const int nb1 = wn * 64;    // GEMM1 n base (256 wide)
    const int nb2 = wn * 32;    // GEMM2 n base (128 wide)
    const uint32_t b1Base = smu + OFF_SW1 + (uint32_t)(nb1 + grp) * 256u + (uint32_t)tig * 4u;
    const uint32_t b2Base = smu + OFF_SW2 + (uint32_t)(nb2 + grp) * 512u + (uint32_t)tig * 4u;

    uint32_t a1Base[4], a2Base[4];
    #pragma unroll
    for (int mf = 0; mf < 4; mf++) {
        a1Base[mf] = sAu + (uint32_t)(64*wm + 16*mf + lr) * 256u;
        a2Base[mf] = sHu + (uint32_t)(64*wm + 16*mf + lr) * 512u;
    }

    // identity-copy prefetch for the first tile
    uint4 cp[8];
    {
        const uint4* xs = (const uint4*)x + (size_t)blockIdx.x * 2048;
        #pragma unroll
        for (int j = 0; j < 8; j++) cp[j] = xs[tid + j * 256];
    }

    // ================= persistent tile loop =================
    for (int t = blockIdx.x; t < NTILES; t += gridDim.x) {
        const int m0 = t << 7;

        // ---- gather A (all 8 warps; 2 threads/row) + event fill ----
        {
            const int r = tid >> 1, q = tid & 1;
            const int pi = pidx[m0 + r];
            const uint32_t rb  = sAu + (uint32_t)r * 256u;
            const uint32_t msk = ((uint32_t)(r & 7)) << 4;
            const float4* src = q ? (const float4*)(gf + (size_t)(((unsigned)pi) & (NE-1)) * NF)
                                  : (const float4*)(x  + (size_t)pi * NF);
            const uint32_t cbase = q ? 128u : 0u;
            #pragma unroll
            for (int c = 0; c < 8; c++) {
                float4 u = src[2*c], v = src[2*c+1];
                sts128(rb + ((cbase + (uint32_t)(c*16)) ^ msk),
                       pack_h2(u.x,u.y), pack_h2(u.z,u.w), pack_h2(v.x,v.y), pack_h2(v.z,v.w));
            }
            if (write_event) {
                int ei = t * 384 + tid;
                out[(size_t)3 * NN * NF + ei] = (float)(ei & (NE - 1));
                if (tid < 128) {
                    int e2 = t * 384 + 256 + tid;
                    out[(size_t)3 * NN * NF + e2] = (float)(e2 & (NE - 1));
                }
            }
        }
        __syncthreads();

        // ---- GEMM1: C1(128x256) = A(128x128) @ W1; copy-stores interleaved ----
        float acc1[4][8][4];
        #pragma unroll
        for (int mf=0; mf<4; mf++)
            #pragma unroll
            for (int nt=0; nt<8; nt++)
                #pragma unroll
                for (int i=0;i<4;i++) acc1[mf][nt][i]=0.f;

        uint4* od = (uint4*)out + (size_t)t * 2048;
        #pragma unroll
        for (int kk = 0; kk < 8; kk++) {
            od[tid + kk * 256] = cp[kk];   // identity copy (data prefetched last tile)
            const uint32_t ksw = (((uint32_t)(kk*32)) + ahi) ^ amask;
            uint32_t A[4][4];
            #pragma unroll
            for (int mf = 0; mf < 4; mf++)
                ldmx4(A[mf][0],A[mf][1],A[mf][2],A[mf][3], a1Base[mf] + ksw);
            const uint32_t k0 = ((uint32_t)(kk*32))      ^ bmask;
            const uint32_t k1 = ((uint32_t)(kk*32 + 16)) ^ bmask;
            #pragma unroll
            for (int nt = 0; nt < 8; nt++) {
                uint32_t b0 = lds32(b1Base + (uint32_t)nt*2048u + k0);
                uint32_t b1 = lds32(b1Base + (uint32_t)nt*2048u + k1);
                #pragma unroll
                for (int mf = 0; mf < 4; mf++)
                    mma16(acc1[mf][nt], A[mf][0],A[mf][1],A[mf][2],A[mf][3], b0, b1);
            }
        }

        // ---- Epilogue 1: bias+relu+pack -> sH, keep own slice in regs ----
        uint32_t hA[4][8], hB[4][8];
        #pragma unroll
        for (int mf=0; mf<4; mf++){
            const uint32_t rb0 = sHu + (uint32_t)(64*wm + 16*mf + grp) * 512u;
            const uint32_t rb1 = rb0 + 8u * 512u;
            #pragma unroll
            for (int nt=0; nt<8; nt++){
                const int c0 = nb1 + nt*8 + 2*tig;
                float bz0 = sb1[c0], bz1 = sb1[c0+1];
                uint32_t p01 = pack_h2(fmaxf(acc1[mf][nt][0]+bz0,0.f), fmaxf(acc1[mf][nt][1]+bz1,0.f));
                uint32_t p23 = pack_h2(fmaxf(acc1[mf][nt][2]+bz0,0.f), fmaxf(acc1[mf][nt][3]+bz1,0.f));
                const uint32_t csw = (((uint32_t)(128*wn + nt*16)) ^ bmask) + (uint32_t)(4*tig);
                sts32(rb0 + csw, p01);
                sts32(rb1 + csw, p23);
                hA[mf][nt] = p01; hB[mf][nt] = p23;
            }
        }
        __syncthreads();

        // ---- GEMM2: C2(128x128) = h(128x256) @ W2; own k-slice from registers ----
        float acc2[4][4][4];
        #pragma unroll
        for (int mf=0; mf<4; mf++)
            #pragma unroll
            for (int nt=0; nt<4; nt++)
                #pragma unroll
                for (int i=0;i<4;i++) acc2[mf][nt][i]=0.f;

        #pragma unroll
        for (int s = 0; s < 16; s++) {
            uint32_t A[4][4];
            if ((s >> 2) == wn) {
                const int kkl = s & 3;
                #pragma unroll
                for (int mf = 0; mf < 4; mf++) {
                    A[mf][0] = hA[mf][2*kkl];   A[mf][1] = hB[mf][2*kkl];
                    A[mf][2] = hA[mf][2*kkl+1]; A[mf][3] = hB[mf][2*kkl+1];
                }
            } else {
                const uint32_t ksw = (((uint32_t)(s*32)) + ahi) ^ amask;
                #pragma unroll
                for (int mf = 0; mf < 4; mf++)
                    ldmx4(A[mf][0],A[mf][1],A[mf][2],A[mf][3], a2Base[mf] + ksw);
            }
            const uint32_t k0 = ((uint32_t)(s*32))      ^ bmask;
            const uint32_t k1 = ((uint32_t)(s*32 + 16)) ^ bmask;
            #pragma unroll
            for (int nt = 0; nt < 4; nt++) {
                uint32_t b0 = lds32(b2Base + (uint32_t)nt*4096u + k0);
                uint32_t b1 = lds32(b2Base + (uint32_t)nt*4096u + k1);
                #pragma unroll
                for (int mf = 0; mf < 4; mf++)
                    mma16(acc2[mf][nt], A[mf][0],A[mf][1],A[mf][2],A[mf][3], b0, b1);
            }
        }

        // ---- prefetch next tile's identity copy ----
        {
            int tn = t + gridDim.x;
            if (tn < NTILES) {
                const uint4* xs = (const uint4*)x + (size_t)tn * 2048;
                #pragma unroll
                for (int j = 0; j < 8; j++) cp[j] = xs[tid + j * 256];
            }
        }

        // ---- Epilogue 2: bias + branch-permuted scatter ----
        const int p  = m0 >> 13;
        const int e0 = m0 & (NE - 1);
        #pragma unroll
        for (int mf=0; mf<4; mf++){
            const int r0 = 64*wm + 16*mf + grp;
            #pragma unroll
            for (int nt=0; nt<4; nt++){
                const int c0 = nb2 + nt*8 + 2*tig;
                const int br = c0 >> 6, fc = c0 & 63;
                const size_t rowbase = (size_t)NN + (size_t)(2*p + br) * NE + (size_t)e0;
                float bz0 = sb2[c0], bz1 = sb2[c0+1];
                float2 v0 = { acc2[mf][nt][0] + bz0, acc2[mf][nt][1] + bz1 };
                float2 v1 = { acc2[mf][nt][2] + bz0, acc2[mf][nt][3] + bz1 };
                *(float2*)(out + (rowbase + r0)     * NF + fc) = v0;
                *(float2*)(out + (rowbase + r0 + 8) * NF + fc) = v1;
            }
        }
        // no trailing barrier needed: SYNC1(next) orders gather-writes after GEMM1 reads,
        // and ep1-next writes to sH happen after all warps passed SYNC1(next) (post-GEMM2).
    }
}

extern "C" void kernel_launch(void* const* d_in, const int* in_sizes, int n_in,
                              void* d_out, int out_size)
{
    const float* x   = (const float*)d_in[0];
    const float* gf  = (const float*)d_in[1];
    const float* W1  = (const float*)d_in[2];
    const float* b1  = (const float*)d_in[3];
    const float* W2  = (const float*)d_in[4];
    const float* b2  = (const float*)d_in[5];
    const int*  pidx = (const int*)d_in[6];
    float* out = (float*)d_out;

    int write_event = (out_size >= (3 * NN * NF + 3 * NN)) ? 1 : 0;

    int dev = 0, nsm = 148;
    cudaGetDevice(&dev);
    cudaDeviceGetAttribute(&nsm, cudaDevAttrMultiProcessorCount, dev);
    if (nsm <= 0 || nsm > NTILES) nsm = 148;

    cudaFuncSetAttribute(fused_h16b, cudaFuncAttributeMaxDynamicSharedMemorySize, SMEM_REQ);
    fused_h16b<<<nsm, NTHREADS, SMEM_REQ>>>(x, gf, W1, b1, W2, b2, pidx, out, write_event);
}